// round 1
// baseline (speedup 1.0000x reference)
#include <cuda_runtime.h>

// DWT Haar L1 loss, fused: loss = (2/N) * sum over 2x2 blocks of
// |a+b+c+d| + |a+b-c-d| + |a-b+c-d| + |a-b-c+d| where a,b,c,d are
// (pred - target) at the 4 block positions. Pure streaming reduction.

__global__ void zero_out_kernel(float* out) { out[0] = 0.0f; }

__global__ void __launch_bounds__(256)
dwt_loss_kernel(const float* __restrict__ pred,
                const float* __restrict__ target,
                float* __restrict__ out,
                int nwork, float scale)
{
    float acc = 0.0f;
    const int stride = gridDim.x * blockDim.x;

    for (int i = blockIdx.x * blockDim.x + threadIdx.x; i < nwork; i += stride) {
        // Each work item: one float4 from row 2r and row 2r+1 of both tensors.
        // Row width = 512 floats; a "pair" spans 1024 floats.
        int pair = i >> 7;      // i / 128  (128 float4 groups per row-pair)
        int xv   = i & 127;
        size_t base = (size_t)pair * 1024 + (size_t)xv * 4;

        float4 p0 = *reinterpret_cast<const float4*>(pred   + base);
        float4 p1 = *reinterpret_cast<const float4*>(pred   + base + 512);
        float4 t0 = *reinterpret_cast<const float4*>(target + base);
        float4 t1 = *reinterpret_cast<const float4*>(target + base + 512);

        // Block 0: columns {x, y}
        float a = p0.x - t0.x;
        float b = p0.y - t0.y;
        float c = p1.x - t1.x;
        float d = p1.y - t1.y;
        float s0 = a + b, s1 = c + d, d0 = a - b, d1 = c - d;
        acc += fabsf(s0 + s1) + fabsf(s0 - s1) + fabsf(d0 + d1) + fabsf(d0 - d1);

        // Block 1: columns {z, w}
        a = p0.z - t0.z;
        b = p0.w - t0.w;
        c = p1.z - t1.z;
        d = p1.w - t1.w;
        s0 = a + b; s1 = c + d; d0 = a - b; d1 = c - d;
        acc += fabsf(s0 + s1) + fabsf(s0 - s1) + fabsf(d0 + d1) + fabsf(d0 - d1);
    }

    // Warp reduction
    #pragma unroll
    for (int o = 16; o > 0; o >>= 1)
        acc += __shfl_down_sync(0xffffffffu, acc, o);

    __shared__ float smem[8];
    int lane = threadIdx.x & 31;
    int wid  = threadIdx.x >> 5;
    if (lane == 0) smem[wid] = acc;
    __syncthreads();

    if (wid == 0) {
        acc = (lane < (blockDim.x >> 5)) ? smem[lane] : 0.0f;
        #pragma unroll
        for (int o = 4; o > 0; o >>= 1)
            acc += __shfl_down_sync(0xffffffffu, acc, o);
        if (lane == 0)
            atomicAdd(out, acc * scale);
    }
}

extern "C" void kernel_launch(void* const* d_in, const int* in_sizes, int n_in,
                              void* d_out, int out_size)
{
    const float* pred   = (const float*)d_in[0];
    const float* target = (const float*)d_in[1];
    float* out = (float*)d_out;

    const int total = in_sizes[0];          // 32*3*512*512 = 25,165,824
    const int nwork = total / 8;            // 8 elements of each tensor per item
    const float scale = 2.0f / (float)total;

    zero_out_kernel<<<1, 1>>>(out);

    const int threads = 256;
    int blocks = 148 * 16;                  // grid-stride; full-chip coverage
    int maxb = (nwork + threads - 1) / threads;
    if (blocks > maxb) blocks = maxb;

    dwt_loss_kernel<<<blocks, threads>>>(pred, target, out, nwork, scale);
}